// round 1
// baseline (speedup 1.0000x reference)
#include <cuda_runtime.h>
#include <math.h>

// Problem constants
#define BB 2
#define SS 2048
#define DM 1024
#define NH 16
#define DK 64
#define INNER 1024
#define MROWS (BB*SS)          // 4096
#define NBKT 32
#define TABW 4095              // delta in [-2047, 2047]

// ---------------- device scratch (static globals: allowed) ----------------
__device__ float g_Q[(size_t)BB*NH*SS*DK];
__device__ float g_K[(size_t)BB*NH*SS*DK];
__device__ float g_V[(size_t)BB*NH*SS*DK];
__device__ float g_ctx[(size_t)BB*SS*INNER];
__device__ float g_biastab[NH*TABW];

// ---------------- bias table: bucket + gather rel_emb ----------------
__global__ void biastab_kernel(const float* __restrict__ rel_emb) {
    int i = blockIdx.x * blockDim.x + threadIdx.x;
    if (i >= TABW) return;
    int delta = i - 2047;          // k - q  (= relative_position)
    int n = -delta;
    int ret = (n < 0) ? 16 : 0;
    int na = n < 0 ? -n : n;
    int bkt;
    if (na < 8) {
        bkt = na;
    } else {
        float v = (logf((float)na * 0.125f) / 2.772588722239781f) * 8.0f;
        int vi = 8 + (int)v;
        bkt = vi > 15 ? 15 : vi;
    }
    bkt += ret;
#pragma unroll
    for (int h = 0; h < NH; ++h)
        g_biastab[h*TABW + i] = __ldg(&rel_emb[bkt*NH + h]);
}

// ---------------- position_bias writer: [1,H,S,S] ----------------
__global__ void pbwrite_kernel(float* __restrict__ pb) {
    int row = blockIdx.x;                 // h*S + q
    int q = row & (SS-1);
    int h = row >> 11;
    const float* tab = g_biastab + h*TABW + (2047 - q);  // tab[k] = bias(k - q)
    float* dst = pb + (size_t)row * SS;
    for (int k4 = threadIdx.x * 4; k4 < SS; k4 += blockDim.x * 4) {
        float4 v;
        v.x = tab[k4 + 0];
        v.y = tab[k4 + 1];
        v.z = tab[k4 + 2];
        v.w = tab[k4 + 3];
        *(float4*)(dst + k4) = v;
    }
}

// ---------------- SGEMM: C[M,N] = A[M,K] @ W[K,N], fp32 ----------------
// mode 0: plain row-major C.  mode 1: QKV remap -> C[((b*16+h)*S + s)*64 + d]
#define TSK 16
__global__ __launch_bounds__(256, 2)
void sgemm_kernel(const float* __restrict__ A, const float* __restrict__ W,
                  float* __restrict__ C, int M, int N, int K, int mode) {
    __shared__ __align__(16) float As[TSK][128];
    __shared__ __align__(16) float Bs[TSK][128];
    int tid = threadIdx.x;
    int bm = blockIdx.y * 128;
    int bn = blockIdx.x * 128;
    int tx = tid & 15, ty = tid >> 4;

    int arow = tid >> 1;
    int acol = (tid & 1) * 8;
    int brow = tid >> 5;            // 0..7
    int bcol = (tid & 31) * 4;
    const float* Aptr = A + (size_t)(bm + arow) * K + acol;
    const float* Bptr = W + (size_t)brow * N + bn + bcol;

    float acc[8][8];
#pragma unroll
    for (int i = 0; i < 8; ++i)
#pragma unroll
        for (int j = 0; j < 8; ++j) acc[i][j] = 0.0f;

    for (int k0 = 0; k0 < K; k0 += TSK) {
        float4 a0 = *(const float4*)(Aptr + k0);
        float4 a1 = *(const float4*)(Aptr + k0 + 4);
        float4 b0 = *(const float4*)(Bptr + (size_t)k0 * N);
        float4 b1 = *(const float4*)(Bptr + (size_t)(k0 + 8) * N);
        __syncthreads();
        As[acol+0][arow] = a0.x; As[acol+1][arow] = a0.y;
        As[acol+2][arow] = a0.z; As[acol+3][arow] = a0.w;
        As[acol+4][arow] = a1.x; As[acol+5][arow] = a1.y;
        As[acol+6][arow] = a1.z; As[acol+7][arow] = a1.w;
        *(float4*)(&Bs[brow][bcol])     = b0;
        *(float4*)(&Bs[brow + 8][bcol]) = b1;
        __syncthreads();
#pragma unroll
        for (int kk = 0; kk < TSK; ++kk) {
            float4 x0 = *(const float4*)(&As[kk][ty*4]);
            float4 x1 = *(const float4*)(&As[kk][ty*4 + 64]);
            float4 y0 = *(const float4*)(&Bs[kk][tx*4]);
            float4 y1 = *(const float4*)(&Bs[kk][tx*4 + 64]);
            float xa[8] = {x0.x,x0.y,x0.z,x0.w,x1.x,x1.y,x1.z,x1.w};
            float yb[8] = {y0.x,y0.y,y0.z,y0.w,y1.x,y1.y,y1.z,y1.w};
#pragma unroll
            for (int i = 0; i < 8; ++i)
#pragma unroll
                for (int j = 0; j < 8; ++j)
                    acc[i][j] += xa[i] * yb[j];
        }
    }

#pragma unroll
    for (int i = 0; i < 8; ++i) {
        int ml = ty*4 + (i & 3) + ((i >> 2) * 64);
        int m = bm + ml;
#pragma unroll
        for (int j = 0; j < 8; ++j) {
            int nl = tx*4 + (j & 3) + ((j >> 2) * 64);
            int n = bn + nl;
            if (mode == 0) {
                C[(size_t)m * N + n] = acc[i][j];
            } else {
                int b = m >> 11, s = m & (SS-1);
                int h = n >> 6,  d = n & 63;
                C[((size_t)(b*NH + h) * SS + s) * DK + d] = acc[i][j];
            }
        }
    }
}

// ---------------- flash attention: 64x64 tiles, fp32 ----------------
// smem layout (floats): Qt[64][68], Kt[64][68], Vs[64][68], Pt[64][68],
// bias_s[2112], mask_s[64]
#define FPAD 68
#define FLASH_SMEM_FLOATS (4*64*FPAD + 2112 + 64)
#define FLASH_SMEM_BYTES (FLASH_SMEM_FLOATS*4)

__global__ __launch_bounds__(256)
void flash_kernel(const float* __restrict__ mask, float* __restrict__ ctx) {
    extern __shared__ __align__(16) float sm[];
    float* Qt     = sm;                 // [d][row]
    float* Kt     = sm + 64*FPAD;       // [d][key]
    float* Vs     = sm + 2*64*FPAD;     // [key][d]
    float* Pt     = sm + 3*64*FPAD;     // [key][row]
    float* bias_s = sm + 4*64*FPAD;     // 2112
    float* mask_s = bias_s + 2112;      // 64

    int tid = threadIdx.x;
    int q0 = blockIdx.x * 64;
    int h  = blockIdx.y;
    int b  = blockIdx.z;
    size_t bh = (size_t)(b*NH + h) * SS * DK;
    const float* Qg = g_Q + bh;
    const float* Kg = g_K + bh;
    const float* Vg = g_V + bh;

    // Load Q tile transposed
    for (int i = tid; i < 64*64; i += 256) {
        int r = i >> 6, d = i & 63;
        Qt[d*FPAD + r] = Qg[(size_t)(q0 + r) * DK + d];
    }
    // Bias slice: bias_s[j] = biastab[h][(1984 - q0) + j]; access: j = k - rl + 63
    for (int j = tid; j < 2112; j += 256)
        bias_s[j] = (j < 2111) ? g_biastab[h*TABW + (1984 - q0) + j] : 0.0f;

    int tx = tid & 15, ty = tid >> 4;
    int r0 = ty * 4, c0 = tx * 4;

    float m_i[4] = {-INFINITY, -INFINITY, -INFINITY, -INFINITY};
    float l_i[4] = {0.f, 0.f, 0.f, 0.f};
    float acc[4][4];
#pragma unroll
    for (int i = 0; i < 4; ++i)
#pragma unroll
        for (int j = 0; j < 4; ++j) acc[i][j] = 0.f;

    for (int kt = 0; kt < SS/64; ++kt) {
        int k0 = kt * 64;
        __syncthreads();   // prev PV done before overwriting K/V
        for (int i = tid; i < 64*64; i += 256) {
            int r = i >> 6, d = i & 63;
            float kv = Kg[(size_t)(k0 + r) * DK + d];
            float vv = Vg[(size_t)(k0 + r) * DK + d];
            Kt[d*FPAD + r] = kv;
            Vs[r*FPAD + d] = vv;
        }
        if (tid < 64) mask_s[tid] = mask[(size_t)b * SS + k0 + tid];
        __syncthreads();

        // scores S = Q K^T
        float s[4][4];
#pragma unroll
        for (int i = 0; i < 4; ++i)
#pragma unroll
            for (int j = 0; j < 4; ++j) s[i][j] = 0.f;
#pragma unroll 8
        for (int kk = 0; kk < 64; ++kk) {
            float4 qa = *(const float4*)(Qt + kk*FPAD + r0);
            float4 kb = *(const float4*)(Kt + kk*FPAD + c0);
            float qq[4] = {qa.x, qa.y, qa.z, qa.w};
            float kv[4] = {kb.x, kb.y, kb.z, kb.w};
#pragma unroll
            for (int i = 0; i < 4; ++i)
#pragma unroll
                for (int j = 0; j < 4; ++j)
                    s[i][j] += qq[i] * kv[j];
        }
        // + bias + mask
#pragma unroll
        for (int i = 0; i < 4; ++i)
#pragma unroll
            for (int j = 0; j < 4; ++j)
                s[i][j] += bias_s[(k0 + c0 + j) + 63 - (r0 + i)] + mask_s[c0 + j];

        // online softmax update (rows shared by 16 lanes with same ty)
#pragma unroll
        for (int i = 0; i < 4; ++i) {
            float rm = fmaxf(fmaxf(s[i][0], s[i][1]), fmaxf(s[i][2], s[i][3]));
#pragma unroll
            for (int off = 8; off > 0; off >>= 1)
                rm = fmaxf(rm, __shfl_xor_sync(0xffffffffu, rm, off, 16));
            float mnew = fmaxf(m_i[i], rm);
            float corr = __expf(m_i[i] - mnew);
            m_i[i] = mnew;
            float rs = 0.f;
#pragma unroll
            for (int j = 0; j < 4; ++j) {
                s[i][j] = __expf(s[i][j] - mnew);
                rs += s[i][j];
            }
#pragma unroll
            for (int off = 8; off > 0; off >>= 1)
                rs += __shfl_xor_sync(0xffffffffu, rs, off, 16);
            l_i[i] = l_i[i] * corr + rs;
#pragma unroll
            for (int j = 0; j < 4; ++j) acc[i][j] *= corr;
#pragma unroll
            for (int j = 0; j < 4; ++j)
                Pt[(c0 + j)*FPAD + (r0 + i)] = s[i][j];
        }
        __syncthreads();

        // O += P V
#pragma unroll 8
        for (int kk = 0; kk < 64; ++kk) {
            float4 pa = *(const float4*)(Pt + kk*FPAD + r0);
            float4 vb = *(const float4*)(Vs + kk*FPAD + c0);
            float pp[4] = {pa.x, pa.y, pa.z, pa.w};
            float vv[4] = {vb.x, vb.y, vb.z, vb.w};
#pragma unroll
            for (int i = 0; i < 4; ++i)
#pragma unroll
                for (int j = 0; j < 4; ++j)
                    acc[i][j] += pp[i] * vv[j];
        }
    }

    // write context [B,S,INNER]
#pragma unroll
    for (int i = 0; i < 4; ++i) {
        float inv = 1.0f / l_i[i];
        float4 o;
        o.x = acc[i][0] * inv; o.y = acc[i][1] * inv;
        o.z = acc[i][2] * inv; o.w = acc[i][3] * inv;
        size_t row = (size_t)b * SS + q0 + r0 + i;
        *(float4*)(g_ctx + 0) ;  // no-op guard removed below
        *(float4*)(ctx + row * INNER + h * DK + c0) = o;
    }
}

// ---------------- launch ----------------
extern "C" void kernel_launch(void* const* d_in, const int* in_sizes, int n_in,
                              void* d_out, int out_size) {
    const float* hidden = (const float*)d_in[0];
    const float* mask   = (const float*)d_in[1];
    const float* Wq     = (const float*)d_in[2];
    const float* Wk     = (const float*)d_in[3];
    const float* Wv     = (const float*)d_in[4];
    const float* Wo     = (const float*)d_in[5];
    const float* rel    = (const float*)d_in[6];
    float* out = (float*)d_out;
    float* pb  = out + (size_t)MROWS * DM;   // position_bias after output

    float *Qp, *Kp, *Vp, *Cp;
    cudaGetSymbolAddress((void**)&Qp, g_Q);
    cudaGetSymbolAddress((void**)&Kp, g_K);
    cudaGetSymbolAddress((void**)&Vp, g_V);
    cudaGetSymbolAddress((void**)&Cp, g_ctx);

    cudaFuncSetAttribute(flash_kernel, cudaFuncAttributeMaxDynamicSharedMemorySize,
                         FLASH_SMEM_BYTES);

    biastab_kernel<<<16, 256>>>(rel);
    pbwrite_kernel<<<NH * SS, 256>>>(pb);

    dim3 ggrid(INNER / 128, MROWS / 128);
    sgemm_kernel<<<ggrid, 256>>>(hidden, Wq, Qp, MROWS, INNER, DM, 1);
    sgemm_kernel<<<ggrid, 256>>>(hidden, Wk, Kp, MROWS, INNER, DM, 1);
    sgemm_kernel<<<ggrid, 256>>>(hidden, Wv, Vp, MROWS, INNER, DM, 1);

    dim3 fgrid(SS / 64, NH, BB);
    flash_kernel<<<fgrid, 256, FLASH_SMEM_BYTES>>>(mask, Cp);

    dim3 ogrid(DM / 128, MROWS / 128);
    sgemm_kernel<<<ogrid, 256>>>(Cp, Wo, out, MROWS, DM, INNER, 0);
}

// round 2
// speedup vs baseline: 1.0078x; 1.0078x over previous
#include <cuda_runtime.h>
#include <math.h>

// Problem constants
#define BB 2
#define SS 2048
#define DM 1024
#define NH 16
#define DK 64
#define INNER 1024
#define MROWS (BB*SS)          // 4096
#define NBKT 32
#define TABW 4095              // delta in [-2047, 2047]

// ---------------- device scratch (static globals: allowed) ----------------
__device__ float g_Q[(size_t)BB*NH*SS*DK];
__device__ float g_K[(size_t)BB*NH*SS*DK];
__device__ float g_V[(size_t)BB*NH*SS*DK];
__device__ float g_ctx[(size_t)BB*SS*INNER];
__device__ float g_biastab[NH*TABW];

// ---------------- bias table: bucket + gather rel_emb ----------------
__global__ void biastab_kernel(const float* __restrict__ rel_emb) {
    int i = blockIdx.x * blockDim.x + threadIdx.x;
    if (i >= TABW) return;
    int delta = i - 2047;          // k - q  (= relative_position)
    int n = -delta;
    int ret = (n < 0) ? 16 : 0;
    int na = n < 0 ? -n : n;
    int bkt;
    if (na < 8) {
        bkt = na;
    } else {
        float v = (logf((float)na * 0.125f) / 2.772588722239781f) * 8.0f;
        int vi = 8 + (int)v;
        bkt = vi > 15 ? 15 : vi;
    }
    bkt += ret;
#pragma unroll
    for (int h = 0; h < NH; ++h)
        g_biastab[h*TABW + i] = __ldg(&rel_emb[bkt*NH + h]);
}

// ---------------- position_bias writer: [1,H,S,S] ----------------
__global__ void pbwrite_kernel(float* __restrict__ pb) {
    int row = blockIdx.x;                 // h*S + q
    int q = row & (SS-1);
    int h = row >> 11;
    const float* tab = g_biastab + h*TABW + (2047 - q);  // tab[k] = bias(k - q)
    float* dst = pb + (size_t)row * SS;
    for (int k4 = threadIdx.x * 4; k4 < SS; k4 += blockDim.x * 4) {
        float4 v;
        v.x = tab[k4 + 0];
        v.y = tab[k4 + 1];
        v.z = tab[k4 + 2];
        v.w = tab[k4 + 3];
        *(float4*)(dst + k4) = v;
    }
}

// ---------------- SGEMM: C[M,N] = A[M,K] @ W[K,N], fp32 ----------------
// mode 0: plain row-major C.  mode 1: QKV remap -> C[((b*16+h)*S + s)*64 + d]
#define TSK 16
__global__ __launch_bounds__(256, 2)
void sgemm_kernel(const float* __restrict__ A, const float* __restrict__ W,
                  float* __restrict__ C, int M, int N, int K, int mode) {
    __shared__ __align__(16) float As[TSK][128];
    __shared__ __align__(16) float Bs[TSK][128];
    int tid = threadIdx.x;
    int bm = blockIdx.y * 128;
    int bn = blockIdx.x * 128;
    int tx = tid & 15, ty = tid >> 4;

    int arow = tid >> 1;
    int acol = (tid & 1) * 8;
    int brow = tid >> 5;            // 0..7
    int bcol = (tid & 31) * 4;
    const float* Aptr = A + (size_t)(bm + arow) * K + acol;
    const float* Bptr = W + (size_t)brow * N + bn + bcol;

    float acc[8][8];
#pragma unroll
    for (int i = 0; i < 8; ++i)
#pragma unroll
        for (int j = 0; j < 8; ++j) acc[i][j] = 0.0f;

    for (int k0 = 0; k0 < K; k0 += TSK) {
        float4 a0 = *(const float4*)(Aptr + k0);
        float4 a1 = *(const float4*)(Aptr + k0 + 4);
        float4 b0 = *(const float4*)(Bptr + (size_t)k0 * N);
        float4 b1 = *(const float4*)(Bptr + (size_t)(k0 + 8) * N);
        __syncthreads();
        As[acol+0][arow] = a0.x; As[acol+1][arow] = a0.y;
        As[acol+2][arow] = a0.z; As[acol+3][arow] = a0.w;
        As[acol+4][arow] = a1.x; As[acol+5][arow] = a1.y;
        As[acol+6][arow] = a1.z; As[acol+7][arow] = a1.w;
        *(float4*)(&Bs[brow][bcol])     = b0;
        *(float4*)(&Bs[brow + 8][bcol]) = b1;
        __syncthreads();
#pragma unroll
        for (int kk = 0; kk < TSK; ++kk) {
            float4 x0 = *(const float4*)(&As[kk][ty*4]);
            float4 x1 = *(const float4*)(&As[kk][ty*4 + 64]);
            float4 y0 = *(const float4*)(&Bs[kk][tx*4]);
            float4 y1 = *(const float4*)(&Bs[kk][tx*4 + 64]);
            float xa[8] = {x0.x,x0.y,x0.z,x0.w,x1.x,x1.y,x1.z,x1.w};
            float yb[8] = {y0.x,y0.y,y0.z,y0.w,y1.x,y1.y,y1.z,y1.w};
#pragma unroll
            for (int i = 0; i < 8; ++i)
#pragma unroll
                for (int j = 0; j < 8; ++j)
                    acc[i][j] += xa[i] * yb[j];
        }
    }

#pragma unroll
    for (int i = 0; i < 8; ++i) {
        int ml = ty*4 + (i & 3) + ((i >> 2) * 64);
        int m = bm + ml;
#pragma unroll
        for (int j = 0; j < 8; ++j) {
            int nl = tx*4 + (j & 3) + ((j >> 2) * 64);
            int n = bn + nl;
            if (mode == 0) {
                C[(size_t)m * N + n] = acc[i][j];
            } else {
                int b = m >> 11, s = m & (SS-1);
                int h = n >> 6,  d = n & 63;
                C[((size_t)(b*NH + h) * SS + s) * DK + d] = acc[i][j];
            }
        }
    }
}

// ---------------- flash attention: 64x64 tiles, fp32 ----------------
// smem layout (floats): Qt[64][68], Kt[64][68], Vs[64][68], Pt[64][68],
// bias_s[2112], mask_s[64]
#define FPAD 68
#define FLASH_SMEM_FLOATS (4*64*FPAD + 2112 + 64)
#define FLASH_SMEM_BYTES (FLASH_SMEM_FLOATS*4)

__global__ __launch_bounds__(256)
void flash_kernel(const float* __restrict__ mask, float* __restrict__ ctx) {
    extern __shared__ __align__(16) float sm[];
    float* Qt     = sm;                 // [d][row]
    float* Kt     = sm + 64*FPAD;       // [d][key]
    float* Vs     = sm + 2*64*FPAD;     // [key][d]
    float* Pt     = sm + 3*64*FPAD;     // [key][row]
    float* bias_s = sm + 4*64*FPAD;     // 2112
    float* mask_s = bias_s + 2112;      // 64

    int tid = threadIdx.x;
    int q0 = blockIdx.x * 64;
    int h  = blockIdx.y;
    int b  = blockIdx.z;
    size_t bh = (size_t)(b*NH + h) * SS * DK;
    const float* Qg = g_Q + bh;
    const float* Kg = g_K + bh;
    const float* Vg = g_V + bh;

    // Load Q tile transposed
    for (int i = tid; i < 64*64; i += 256) {
        int r = i >> 6, d = i & 63;
        Qt[d*FPAD + r] = Qg[(size_t)(q0 + r) * DK + d];
    }
    // Bias slice: bias_s[j] = biastab[h][(1984 - q0) + j]; access: j = k - rl + 63
    for (int j = tid; j < 2112; j += 256)
        bias_s[j] = (j < 2111) ? g_biastab[h*TABW + (1984 - q0) + j] : 0.0f;

    int tx = tid & 15, ty = tid >> 4;
    int r0 = ty * 4, c0 = tx * 4;

    float m_i[4] = {-INFINITY, -INFINITY, -INFINITY, -INFINITY};
    float l_i[4] = {0.f, 0.f, 0.f, 0.f};
    float acc[4][4];
#pragma unroll
    for (int i = 0; i < 4; ++i)
#pragma unroll
        for (int j = 0; j < 4; ++j) acc[i][j] = 0.f;

    for (int kt = 0; kt < SS/64; ++kt) {
        int k0 = kt * 64;
        __syncthreads();   // prev PV done before overwriting K/V
        for (int i = tid; i < 64*64; i += 256) {
            int r = i >> 6, d = i & 63;
            float kv = Kg[(size_t)(k0 + r) * DK + d];
            float vv = Vg[(size_t)(k0 + r) * DK + d];
            Kt[d*FPAD + r] = kv;
            Vs[r*FPAD + d] = vv;
        }
        if (tid < 64) mask_s[tid] = mask[(size_t)b * SS + k0 + tid];
        __syncthreads();

        // scores S = Q K^T
        float s[4][4];
#pragma unroll
        for (int i = 0; i < 4; ++i)
#pragma unroll
            for (int j = 0; j < 4; ++j) s[i][j] = 0.f;
#pragma unroll 8
        for (int kk = 0; kk < 64; ++kk) {
            float4 qa = *(const float4*)(Qt + kk*FPAD + r0);
            float4 kb = *(const float4*)(Kt + kk*FPAD + c0);
            float qq[4] = {qa.x, qa.y, qa.z, qa.w};
            float kv[4] = {kb.x, kb.y, kb.z, kb.w};
#pragma unroll
            for (int i = 0; i < 4; ++i)
#pragma unroll
                for (int j = 0; j < 4; ++j)
                    s[i][j] += qq[i] * kv[j];
        }
        // + bias + mask
#pragma unroll
        for (int i = 0; i < 4; ++i)
#pragma unroll
            for (int j = 0; j < 4; ++j)
                s[i][j] += bias_s[(k0 + c0 + j) + 63 - (r0 + i)] + mask_s[c0 + j];

        // online softmax update (rows shared by 16 lanes with same ty)
#pragma unroll
        for (int i = 0; i < 4; ++i) {
            float rm = fmaxf(fmaxf(s[i][0], s[i][1]), fmaxf(s[i][2], s[i][3]));
#pragma unroll
            for (int off = 8; off > 0; off >>= 1)
                rm = fmaxf(rm, __shfl_xor_sync(0xffffffffu, rm, off, 16));
            float mnew = fmaxf(m_i[i], rm);
            float corr = __expf(m_i[i] - mnew);
            m_i[i] = mnew;
            float rs = 0.f;
#pragma unroll
            for (int j = 0; j < 4; ++j) {
                s[i][j] = __expf(s[i][j] - mnew);
                rs += s[i][j];
            }
#pragma unroll
            for (int off = 8; off > 0; off >>= 1)
                rs += __shfl_xor_sync(0xffffffffu, rs, off, 16);
            l_i[i] = l_i[i] * corr + rs;
#pragma unroll
            for (int j = 0; j < 4; ++j) acc[i][j] *= corr;
#pragma unroll
            for (int j = 0; j < 4; ++j)
                Pt[(c0 + j)*FPAD + (r0 + i)] = s[i][j];
        }
        __syncthreads();

        // O += P V
#pragma unroll 8
        for (int kk = 0; kk < 64; ++kk) {
            float4 pa = *(const float4*)(Pt + kk*FPAD + r0);
            float4 vb = *(const float4*)(Vs + kk*FPAD + c0);
            float pp[4] = {pa.x, pa.y, pa.z, pa.w};
            float vv[4] = {vb.x, vb.y, vb.z, vb.w};
#pragma unroll
            for (int i = 0; i < 4; ++i)
#pragma unroll
                for (int j = 0; j < 4; ++j)
                    acc[i][j] += pp[i] * vv[j];
        }
    }

    // write context [B,S,INNER]
#pragma unroll
    for (int i = 0; i < 4; ++i) {
        float inv = 1.0f / l_i[i];
        float4 o;
        o.x = acc[i][0] * inv; o.y = acc[i][1] * inv;
        o.z = acc[i][2] * inv; o.w = acc[i][3] * inv;
        size_t row = (size_t)b * SS + q0 + r0 + i;
        *(float4*)(g_ctx + 0) ;  // no-op guard removed below
        *(float4*)(ctx + row * INNER + h * DK + c0) = o;
    }
}

// ---------------- launch ----------------
extern "C" void kernel_launch(void* const* d_in, const int* in_sizes, int n_in,
                              void* d_out, int out_size) {
    const float* hidden = (const float*)d_in[0];
    const float* mask   = (const float*)d_in[1];
    const float* Wq     = (const float*)d_in[2];
    const float* Wk     = (const float*)d_in[3];
    const float* Wv     = (const float*)d_in[4];
    const float* Wo     = (const float*)d_in[5];
    const float* rel    = (const float*)d_in[6];
    float* out = (float*)d_out;
    float* pb  = out + (size_t)MROWS * DM;   // position_bias after output

    float *Qp, *Kp, *Vp, *Cp;
    cudaGetSymbolAddress((void**)&Qp, g_Q);
    cudaGetSymbolAddress((void**)&Kp, g_K);
    cudaGetSymbolAddress((void**)&Vp, g_V);
    cudaGetSymbolAddress((void**)&Cp, g_ctx);

    cudaFuncSetAttribute(flash_kernel, cudaFuncAttributeMaxDynamicSharedMemorySize,
                         FLASH_SMEM_BYTES);

    biastab_kernel<<<16, 256>>>(rel);
    pbwrite_kernel<<<NH * SS, 256>>>(pb);

    dim3 ggrid(INNER / 128, MROWS / 128);
    sgemm_kernel<<<ggrid, 256>>>(hidden, Wq, Qp, MROWS, INNER, DM, 1);
    sgemm_kernel<<<ggrid, 256>>>(hidden, Wk, Kp, MROWS, INNER, DM, 1);
    sgemm_kernel<<<ggrid, 256>>>(hidden, Wv, Vp, MROWS, INNER, DM, 1);

    dim3 fgrid(SS / 64, NH, BB);
    flash_kernel<<<fgrid, 256, FLASH_SMEM_BYTES>>>(mask, Cp);

    dim3 ogrid(DM / 128, MROWS / 128);
    sgemm_kernel<<<ogrid, 256>>>(Cp, Wo, out, MROWS, DM, INNER, 0);
}

// round 4
// speedup vs baseline: 2.3375x; 2.3193x over previous
#include <cuda_runtime.h>
#include <cuda_bf16.h>
#include <math.h>
#include <stdint.h>

#define BB 2
#define SS 2048
#define DM 1024
#define NH 16
#define DK 64
#define MROWS 4096
#define TABW 4095

typedef __nv_bfloat16 bf16;

// ---------------- device scratch ----------------
__device__ bf16 g_Ah[(size_t)MROWS*DM];
__device__ bf16 g_Al[(size_t)MROWS*DM];
__device__ bf16 g_Wth[(size_t)4*DM*DM];
__device__ bf16 g_Wtl[(size_t)4*DM*DM];
__device__ bf16 g_Qh[(size_t)MROWS*DM];
__device__ bf16 g_Ql[(size_t)MROWS*DM];
__device__ bf16 g_Kh[(size_t)MROWS*DM];
__device__ bf16 g_Kl[(size_t)MROWS*DM];
__device__ bf16 g_Vth[(size_t)MROWS*DM];
__device__ bf16 g_Vtl[(size_t)MROWS*DM];
__device__ bf16 g_Ch[(size_t)MROWS*DM];
__device__ bf16 g_Cl[(size_t)MROWS*DM];
__device__ float g_biastab[NH*TABW + 64];   // padded (OOB-safe window staging)

// ---------------- helpers ----------------
__device__ __forceinline__ uint32_t smem_u32(const void* p){
    uint32_t a;
    asm("{ .reg .u64 t; cvta.to.shared.u64 t, %1; cvt.u32.u64 %0, t; }" : "=r"(a) : "l"(p));
    return a;
}
__device__ __forceinline__ void cpa16(uint32_t d, const void* s){
    asm volatile("cp.async.cg.shared.global [%0], [%1], 16;" :: "r"(d), "l"(s));
}
__device__ __forceinline__ void cpa4(uint32_t d, const void* s){
    asm volatile("cp.async.ca.shared.global [%0], [%1], 4;" :: "r"(d), "l"(s));
}
#define CPA_COMMIT() asm volatile("cp.async.commit_group;" ::: "memory")
#define CPA_WAIT1()  asm volatile("cp.async.wait_group 1;" ::: "memory")
#define CPA_WAIT0()  asm volatile("cp.async.wait_group 0;" ::: "memory")

__device__ __forceinline__ void mma_bf(float* c, const uint32_t* a, uint32_t b0, uint32_t b1){
    asm volatile("mma.sync.aligned.m16n8k16.row.col.f32.bf16.bf16.f32 "
        "{%0,%1,%2,%3}, {%4,%5,%6,%7}, {%8,%9}, {%0,%1,%2,%3};"
        : "+f"(c[0]), "+f"(c[1]), "+f"(c[2]), "+f"(c[3])
        : "r"(a[0]), "r"(a[1]), "r"(a[2]), "r"(a[3]), "r"(b0), "r"(b1));
}
__device__ __forceinline__ uint32_t pack2(float x0, float x1){
    uint32_t r;
    asm("cvt.rn.bf16x2.f32 %0, %1, %2;" : "=r"(r) : "f"(x1), "f"(x0));
    return r;
}
__device__ __forceinline__ void split2(float x0, float x1, uint32_t& hh, uint32_t& ll){
    hh = pack2(x0, x1);
    float h0 = __uint_as_float(hh << 16);
    float h1 = __uint_as_float(hh & 0xffff0000u);
    ll = pack2(x0 - h0, x1 - h1);
}

// ---------------- bias table ----------------
__global__ void biastab_kernel(const float* __restrict__ rel_emb) {
    int i = blockIdx.x * blockDim.x + threadIdx.x;
    if (i >= TABW) return;
    int delta = i - 2047;
    int n = -delta;
    int ret = (n < 0) ? 16 : 0;
    int na = n < 0 ? -n : n;
    int bkt;
    if (na < 8) bkt = na;
    else {
        float v = (logf((float)na * 0.125f) / 2.772588722239781f) * 8.0f;
        int vi = 8 + (int)v;
        bkt = vi > 15 ? 15 : vi;
    }
    bkt += ret;
#pragma unroll
    for (int hh = 0; hh < NH; ++hh)
        g_biastab[hh*TABW + i] = __ldg(&rel_emb[bkt*NH + hh]);
}

__global__ void pbwrite_kernel(float* __restrict__ pb) {
    int row = blockIdx.x;
    int q = row & (SS-1);
    int hh = row >> 11;
    const float* tab = g_biastab + hh*TABW + (2047 - q);
    float* dst = pb + (size_t)row * SS;
    for (int k4 = threadIdx.x * 4; k4 < SS; k4 += blockDim.x * 4) {
        float4 v;
        v.x = tab[k4+0]; v.y = tab[k4+1]; v.z = tab[k4+2]; v.w = tab[k4+3];
        *(float4*)(dst + k4) = v;
    }
}

__global__ void split_kernel(const float* __restrict__ x, bf16* __restrict__ hi, bf16* __restrict__ lo, int n) {
    int i = (blockIdx.x * blockDim.x + threadIdx.x) * 4;
    if (i >= n) return;
    float4 v = *(const float4*)(x + i);
    float vv[4] = {v.x, v.y, v.z, v.w};
    bf16 hb[4], lb[4];
#pragma unroll
    for (int e = 0; e < 4; ++e) {
        hb[e] = __float2bfloat16(vv[e]);
        lb[e] = __float2bfloat16(vv[e] - __bfloat162float(hb[e]));
    }
    *(uint2*)(hi + i) = *(uint2*)hb;
    *(uint2*)(lo + i) = *(uint2*)lb;
}

__global__ void wtrans_kernel(const float* __restrict__ W, bf16* __restrict__ Th, bf16* __restrict__ Tl) {
    __shared__ float sm[32][33];
    int n0 = blockIdx.x * 32, k0 = blockIdx.y * 32;
    int tx = threadIdx.x, ty = threadIdx.y;
#pragma unroll
    for (int i = 0; i < 32; i += 8)
        sm[ty + i][tx] = W[(size_t)(k0 + ty + i) * DM + n0 + tx];
    __syncthreads();
#pragma unroll
    for (int i = 0; i < 32; i += 8) {
        float x = sm[tx][ty + i];
        bf16 hb = __float2bfloat16(x);
        bf16 lb = __float2bfloat16(x - __bfloat162float(hb));
        Th[(size_t)(n0 + ty + i) * DM + k0 + tx] = hb;
        Tl[(size_t)(n0 + ty + i) * DM + k0 + tx] = lb;
    }
}

// ---------------- mma.sync GEMM: C = A[M,K] @ Bt[N,K]^T, 3x bf16 split ----------------
#define MMP 72                    // smem row pitch in bf16
#define MMT (128*MMP*2)           // one tile: 18432 B
#define MMB (4*MMT)               // buffer (Ah,Al,Bh,Bl): 73728 B
#define MM_SMEM (2*MMB)           // 147456 B

__global__ void __launch_bounds__(256)
mm_kernel(const bf16* __restrict__ Ah, const bf16* __restrict__ Al,
          const bf16* __restrict__ Bh, const bf16* __restrict__ Bl,
          float* __restrict__ outF, bf16* __restrict__ outH, bf16* __restrict__ outL,
          int K, int mode) {
    extern __shared__ char smem[];
    int tid = threadIdx.x, lane = tid & 31, wid = tid >> 5;
    int g = lane >> 2, t = lane & 3;
    int wm = wid >> 2, wn = wid & 3;
    int bn = blockIdx.x * 128, bm = blockIdx.y * 128;

    int row = tid >> 1, half = tid & 1;
    const bf16* gsrc[4];
    gsrc[0] = Ah + (size_t)(bm+row)*K + half*32;
    gsrc[1] = Al + (size_t)(bm+row)*K + half*32;
    gsrc[2] = Bh + (size_t)(bn+row)*K + half*32;
    gsrc[3] = Bl + (size_t)(bn+row)*K + half*32;
    uint32_t sbase = smem_u32(smem);
    uint32_t sdst = sbase + row*(MMP*2) + half*64;

    float acc[4][4][4];
#pragma unroll
    for (int i=0;i<4;++i)
#pragma unroll
        for (int j=0;j<4;++j)
#pragma unroll
            for (int r=0;r<4;++r) acc[i][j][r]=0.f;

    int nst = K / 64;
    auto stage = [&](int s, int bufI){
        uint32_t db = sdst + bufI*MMB;
#pragma unroll
        for (int a=0;a<4;++a){
            const bf16* src = gsrc[a] + s*64;
#pragma unroll
            for (int j=0;j<4;++j)
                cpa16(db + a*MMT + j*16, src + j*8);
        }
        CPA_COMMIT();
    };
    stage(0, 0);
    int buf = 0;
    for (int s=0; s<nst; ++s){
        if (s+1 < nst){ stage(s+1, buf^1); CPA_WAIT1(); }
        else CPA_WAIT0();
        __syncthreads();
        const bf16* sAh = (const bf16*)(smem + buf*MMB);
        const bf16* sAl = sAh + 128*MMP;
        const bf16* sBh = sAl + 128*MMP;
        const bf16* sBl = sBh + 128*MMP;
#pragma unroll
        for (int kk=0; kk<4; ++kk){
            uint32_t fah[4][4], fal[4][4];
#pragma unroll
            for (int mi=0; mi<4; ++mi){
                int ra = (wm*64 + mi*16 + g)*MMP + kk*16 + t*2;
                fah[mi][0] = *(const uint32_t*)(sAh + ra);
                fah[mi][1] = *(const uint32_t*)(sAh + ra + 8*MMP);
                fah[mi][2] = *(const uint32_t*)(sAh + ra + 8);
                fah[mi][3] = *(const uint32_t*)(sAh + ra + 8*MMP + 8);
                fal[mi][0] = *(const uint32_t*)(sAl + ra);
                fal[mi][1] = *(const uint32_t*)(sAl + ra + 8*MMP);
                fal[mi][2] = *(const uint32_t*)(sAl + ra + 8);
                fal[mi][3] = *(const uint32_t*)(sAl + ra + 8*MMP + 8);
            }
#pragma unroll
            for (int ni=0; ni<4; ++ni){
                int rb = (wn*32 + ni*8 + g)*MMP + kk*16 + t*2;
                uint32_t bh0 = *(const uint32_t*)(sBh + rb);
                uint32_t bh1 = *(const uint32_t*)(sBh + rb + 8);
                uint32_t bl0 = *(const uint32_t*)(sBl + rb);
                uint32_t bl1 = *(const uint32_t*)(sBl + rb + 8);
#pragma unroll
                for (int mi=0; mi<4; ++mi){
                    mma_bf(acc[mi][ni], fah[mi], bh0, bh1);
                    mma_bf(acc[mi][ni], fah[mi], bl0, bl1);
                    mma_bf(acc[mi][ni], fal[mi], bh0, bh1);
                }
            }
        }
        __syncthreads();
        buf ^= 1;
    }

    // epilogue
#pragma unroll
    for (int mi=0; mi<4; ++mi){
#pragma unroll
        for (int ni=0; ni<4; ++ni){
            float* c = acc[mi][ni];
            int r0 = bm + wm*64 + mi*16 + g;
            int col = bn + wn*32 + ni*8 + t*2;
            if (mode == 0){
                float2 v0; v0.x = c[0]; v0.y = c[1];
                float2 v1; v1.x = c[2]; v1.y = c[3];
                *(float2*)(outF + (size_t)r0*DM + col) = v0;
                *(float2*)(outF + (size_t)(r0+8)*DM + col) = v1;
            } else if (mode == 1){
                int hh = col >> 6, d = col & 63;
#pragma unroll
                for (int hp=0; hp<2; ++hp){
                    int m = r0 + hp*8;
                    size_t ob = (((size_t)(m>>11)*NH + hh)*SS + (m & (SS-1)))*DK + d;
                    uint32_t ph_, pl_;
                    split2(c[hp*2], c[hp*2+1], ph_, pl_);
                    *(uint32_t*)(outH + ob) = ph_;
                    *(uint32_t*)(outL + ob) = pl_;
                }
            } else {
                int hh = col >> 6, d = col & 63;
#pragma unroll
                for (int hp=0; hp<2; ++hp){
                    int m = r0 + hp*8;
                    int bI = m >> 11, sI = m & (SS-1);
#pragma unroll
                    for (int e=0; e<2; ++e){
                        float x = c[hp*2+e];
                        bf16 hb = __float2bfloat16(x);
                        bf16 lb = __float2bfloat16(x - __bfloat162float(hb));
                        size_t ob = ((size_t)(bI*NH + hh)*DK + (d+e))*SS + sI;
                        outH[ob] = hb; outL[ob] = lb;
                    }
                }
            }
        }
    }
}

// ---------------- mma.sync flash attention ----------------
#define FQP 72
#define FKT 18432          // K tile (128 x pitch72 bf16)
#define FVT 17408          // V tile (64 x pitch136 bf16)
#define FBUF (2*FKT + 2*FVT + 1024)         // 72704: KH,KL,VH,VL,biaswin
#define F_B0 36864                          // after QH+QL
#define F_MASK (F_B0 + 2*FBUF)              // 182272, 8192 B
#define F_RS  (F_MASK + 8192)               // 190464, 1024 B
#define F_RED F_B0                          // reuse buf0 (128*68*4 = 34816 B)
#define F_SMEM (F_RS + 1024)                // 191488

__global__ void __launch_bounds__(256)
flash_kernel(const float* __restrict__ mask){
    extern __shared__ char smem[];
    int tid = threadIdx.x, lane = tid & 31, wid = tid >> 5;
    int g = lane >> 2, t = lane & 3;
    int wm = wid & 3, wn = wid >> 2;     // 4 x 2
    int q0 = blockIdx.x * 128, h = blockIdx.y, b = blockIdx.z;
    size_t bhI = (size_t)(b*NH + h);
    uint32_t sbase = smem_u32(smem);

    // stage Q (once)
    {
        int row = tid >> 1, half = tid & 1;
        const uint4* ph_ = (const uint4*)(g_Qh + (bhI*SS + q0 + row)*DK + half*32);
        const uint4* pl_ = (const uint4*)(g_Ql + (bhI*SS + q0 + row)*DK + half*32);
        uint4* dh = (uint4*)(smem + row*(FQP*2) + half*64);
        uint4* dl = (uint4*)(smem + FKT + row*(FQP*2) + half*64);
#pragma unroll
        for (int j=0;j<4;++j){ dh[j]=ph_[j]; dl[j]=pl_[j]; }
    }
    for (int i=tid; i<SS; i+=256)
        ((float*)(smem+F_MASK))[i] = mask[(size_t)b*SS + i];

    auto stage = [&](int c, int bufI){
        uint32_t B0 = sbase + F_B0 + bufI*FBUF;
        int k0 = c*128;
        int row = tid >> 1, half = tid & 1;
        const bf16* kh = g_Kh + (bhI*SS + k0 + row)*DK + half*32;
        const bf16* kl = g_Kl + (bhI*SS + k0 + row)*DK + half*32;
        uint32_t dk = B0 + row*144 + half*64;
#pragma unroll
        for (int j=0;j<4;++j){
            cpa16(dk + j*16, kh + j*8);
            cpa16(dk + FKT + j*16, kl + j*8);
        }
        int vrow = tid >> 2, vq = tid & 3;
        const bf16* vh = g_Vth + (bhI*DK + vrow)*SS + k0 + vq*32;
        const bf16* vl = g_Vtl + (bhI*DK + vrow)*SS + k0 + vq*32;
        uint32_t dv = B0 + 2*FKT + vrow*272 + vq*64;
#pragma unroll
        for (int j=0;j<4;++j){
            cpa16(dv + j*16, vh + j*8);
            cpa16(dv + FVT + j*16, vl + j*8);
        }
        cpa4(B0 + 2*FKT + 2*FVT + tid*4, g_biastab + h*TABW + 1920 + k0 - q0 + tid);
        CPA_COMMIT();
    };

    float oacc[2][8][4];
#pragma unroll
    for (int i=0;i<2;++i)
#pragma unroll
        for (int j=0;j<8;++j)
#pragma unroll
            for (int r=0;r<4;++r) oacc[i][j][r]=0.f;
    float rowsum[4] = {0.f,0.f,0.f,0.f};

    stage(0,0);
    int buf = 0;
    for (int c=0;c<16;++c){
        if (c+1 < 16){ stage(c+1, buf^1); CPA_WAIT1(); }
        else CPA_WAIT0();
        __syncthreads();
        const char* B0 = smem + F_B0 + buf*FBUF;
        const bf16* sKh = (const bf16*)B0;
        const bf16* sKl = (const bf16*)(B0 + FKT);
        const bf16* sVh = (const bf16*)(B0 + 2*FKT);
        const bf16* sVl = (const bf16*)(B0 + 2*FKT + FVT);
        const float* bw = (const float*)(B0 + 2*FKT + 2*FVT);
        const float* msk = (const float*)(smem + F_MASK) + c*128;
        const bf16* sQh = (const bf16*)smem;
        const bf16* sQl = (const bf16*)(smem + FKT);

        float sacc[2][8][4];
#pragma unroll
        for (int i=0;i<2;++i)
#pragma unroll
            for (int j=0;j<8;++j)
#pragma unroll
                for (int r=0;r<4;++r) sacc[i][j][r]=0.f;

#pragma unroll
        for (int kk=0;kk<4;++kk){
            uint32_t fqh[2][4], fql[2][4];
#pragma unroll
            for (int mi=0;mi<2;++mi){
                int ra = (wm*32 + mi*16 + g)*FQP + kk*16 + t*2;
                fqh[mi][0] = *(const uint32_t*)(sQh + ra);
                fqh[mi][1] = *(const uint32_t*)(sQh + ra + 8*FQP);
                fqh[mi][2] = *(const uint32_t*)(sQh + ra + 8);
                fqh[mi][3] = *(const uint32_t*)(sQh + ra + 8*FQP + 8);
                fql[mi][0] = *(const uint32_t*)(sQl + ra);
                fql[mi][1] = *(const uint32_t*)(sQl + ra + 8*FQP);
                fql[mi][2] = *(const uint32_t*)(sQl + ra + 8);
                fql[mi][3] = *(const uint32_t*)(sQl + ra + 8*FQP + 8);
            }
#pragma unroll
            for (int ni=0;ni<8;++ni){
                int rb = (wn*64 + ni*8 + g)*FQP + kk*16 + t*2;
                uint32_t b0h = *(const uint32_t*)(sKh + rb);
                uint32_t b1h = *(const uint32_t*)(sKh + rb + 8);
                uint32_t b0l = *(const uint32_t*)(sKl + rb);
                uint32_t b1l = *(const uint32_t*)(sKl + rb + 8);
#pragma unroll
                for (int mi=0;mi<2;++mi){
                    mma_bf(sacc[mi][ni], fqh[mi], b0h, b1h);
                    mma_bf(sacc[mi][ni], fqh[mi], b0l, b1l);
                    mma_bf(sacc[mi][ni], fql[mi], b0h, b1h);
                }
            }
        }

        // softmax (fixed shift) + in-register repack S-frags -> P A-frags
        float bv[11][2];
        int base2 = 127 + wn*64 - wm*32 - g + t*2;
#pragma unroll
        for (int d8=0; d8<11; ++d8){
            bv[d8][0] = bw[base2 + 8*(d8-3)];
            bv[d8][1] = bw[base2 + 8*(d8-3) + 1];
        }
        float mv[8][2];
#pragma unroll
        for (int ni=0;ni<8;++ni){
            mv[ni][0] = msk[wn*64 + ni*8 + t*2];
            mv[ni][1] = msk[wn*64 + ni*8 + t*2 + 1];
        }
        uint32_t fph[2][4][4], fpl[2][4][4];
#pragma unroll
        for (int mi=0;mi<2;++mi){
#pragma unroll
            for (int nj=0;nj<4;++nj){
#pragma unroll
                for (int sub=0;sub<2;++sub){
                    int ni = nj*2 + sub;
                    int d0 = ni - mi*2 + 3;
                    int d1 = ni - mi*2 + 2;
                    float p00 = __expf(sacc[mi][ni][0] + bv[d0][0] + mv[ni][0] - 40.f);
                    float p01 = __expf(sacc[mi][ni][1] + bv[d0][1] + mv[ni][1] - 40.f);
                    float p10 = __expf(sacc[mi][ni][2] + bv[d1][0] + mv[ni][0] - 40.f);
                    float p11 = __expf(sacc[mi][ni][3] + bv[d1][1] + mv[ni][1] - 40.f);
                    rowsum[mi*2+0] += p00 + p01;
                    rowsum[mi*2+1] += p10 + p11;
                    uint32_t h0,l0,h1,l1;
                    split2(p00, p01, h0, l0);
                    split2(p10, p11, h1, l1);
                    fph[mi][nj][sub*2+0] = h0; fph[mi][nj][sub*2+1] = h1;
                    fpl[mi][nj][sub*2+0] = l0; fpl[mi][nj][sub*2+1] = l1;
                }
            }
        }

        // O += P V  (this warp's 64-key slice)
#pragma unroll
        for (int j=0;j<4;++j){
#pragma unroll
            for (int ni=0;ni<8;++ni){
                int rv = (ni*8 + g)*136 + wn*64 + j*16 + t*2;
                uint32_t v0h = *(const uint32_t*)(sVh + rv);
                uint32_t v1h = *(const uint32_t*)(sVh + rv + 8);
                uint32_t v0l = *(const uint32_t*)(sVl + rv);
                uint32_t v1l = *(const uint32_t*)(sVl + rv + 8);
#pragma unroll
                for (int mi=0;mi<2;++mi){
                    mma_bf(oacc[mi][ni], fph[mi][j], v0h, v1h);
                    mma_bf(oacc[mi][ni], fph[mi][j], v0l, v1l);
                    mma_bf(oacc[mi][ni], fpl[mi][j], v0h, v1h);
                }
            }
        }
        __syncthreads();
        buf ^= 1;
    }

    // rowsum reduce across quad lanes, publish per wn-group
#pragma unroll
    for (int i=0;i<4;++i){
        rowsum[i] += __shfl_xor_sync(0xffffffffu, rowsum[i], 1);
        rowsum[i] += __shfl_xor_sync(0xffffffffu, rowsum[i], 2);
    }
    {
        float* rs = (float*)(smem + F_RS) + wn*128;
        if (t == 0){
#pragma unroll
            for (int i=0;i<4;++i)
                rs[wm*32 + (i>>1)*16 + g + (i&1)*8] = rowsum[i];
        }
    }
    __syncthreads();
    float* red = (float*)(smem + F_RED);
    if (wn == 1){
#pragma unroll
        for (int mi=0;mi<2;++mi)
#pragma unroll
            for (int ni=0;ni<8;++ni){
                int r0 = wm*32 + mi*16 + g, col = ni*8 + t*2;
                float2 v0; v0.x = oacc[mi][ni][0]; v0.y = oacc[mi][ni][1];
                float2 v1; v1.x = oacc[mi][ni][2]; v1.y = oacc[mi][ni][3];
                *(float2*)(red + r0*68 + col) = v0;
                *(float2*)(red + (r0+8)*68 + col) = v1;
            }
    }
    __syncthreads();
    if (wn == 0){
        const float* rs0 = (const float*)(smem + F_RS);
#pragma unroll
        for (int mi=0;mi<2;++mi)
#pragma unroll
            for (int ni=0;ni<8;++ni){
                int r0 = wm*32 + mi*16 + g, col = ni*8 + t*2;
                float2 a0 = *(float2*)(red + r0*68 + col);
                float2 a1 = *(float2*)(red + (r0+8)*68 + col);
                float i0 = 1.f/(rs0[r0] + rs0[128 + r0]);
                float i1 = 1.f/(rs0[r0+8] + rs0[128 + r0+8]);
                float o0 = (oacc[mi][ni][0] + a0.x)*i0, o1 = (oacc[mi][ni][1] + a0.y)*i0;
                float o2 = (oacc[mi][ni][2] + a1.x)*i1, o3 = (oacc[mi][ni][3] + a1.y)*i1;
                uint32_t hh_, ll_;
                size_t ob0 = ((size_t)b*SS + q0 + r0)*DM + h*DK + col;
                split2(o0, o1, hh_, ll_);
                *(uint32_t*)(g_Ch + ob0) = hh_;
                *(uint32_t*)(g_Cl + ob0) = ll_;
                size_t ob1 = ((size_t)b*SS + q0 + r0 + 8)*DM + h*DK + col;
                split2(o2, o3, hh_, ll_);
                *(uint32_t*)(g_Ch + ob1) = hh_;
                *(uint32_t*)(g_Cl + ob1) = ll_;
            }
    }
}

// ---------------- launch ----------------
extern "C" void kernel_launch(void* const* d_in, const int* in_sizes, int n_in,
                              void* d_out, int out_size) {
    const float* hidden = (const float*)d_in[0];
    const float* mask   = (const float*)d_in[1];
    const float* Wq     = (const float*)d_in[2];
    const float* Wk     = (const float*)d_in[3];
    const float* Wv     = (const float*)d_in[4];
    const float* Wo     = (const float*)d_in[5];
    const float* rel    = (const float*)d_in[6];
    float* out = (float*)d_out;
    float* pb  = out + (size_t)MROWS * DM;

    bf16 *Ahp,*Alp,*Wthp,*Wtlp,*Qhp,*Qlp,*Khp,*Klp,*Vthp,*Vtlp,*Chp,*Clp;
    cudaGetSymbolAddress((void**)&Ahp, g_Ah);
    cudaGetSymbolAddress((void**)&Alp, g_Al);
    cudaGetSymbolAddress((void**)&Wthp, g_Wth);
    cudaGetSymbolAddress((void**)&Wtlp, g_Wtl);
    cudaGetSymbolAddress((void**)&Qhp, g_Qh);
    cudaGetSymbolAddress((void**)&Qlp, g_Ql);
    cudaGetSymbolAddress((void**)&Khp, g_Kh);
    cudaGetSymbolAddress((void**)&Klp, g_Kl);
    cudaGetSymbolAddress((void**)&Vthp, g_Vth);
    cudaGetSymbolAddress((void**)&Vtlp, g_Vtl);
    cudaGetSymbolAddress((void**)&Chp, g_Ch);
    cudaGetSymbolAddress((void**)&Clp, g_Cl);

    cudaFuncSetAttribute(mm_kernel, cudaFuncAttributeMaxDynamicSharedMemorySize, MM_SMEM);
    cudaFuncSetAttribute(flash_kernel, cudaFuncAttributeMaxDynamicSharedMemorySize, F_SMEM);

    biastab_kernel<<<16, 256>>>(rel);
    pbwrite_kernel<<<NH * SS, 256>>>(pb);

    split_kernel<<<MROWS * DM / 1024, 256>>>(hidden, Ahp, Alp, MROWS * DM);
    dim3 wg(DM/32, DM/32), wb(32, 8);
    wtrans_kernel<<<wg, wb>>>(Wq, Wthp,                   Wtlp);
    wtrans_kernel<<<wg, wb>>>(Wk, Wthp + (size_t)DM*DM,   Wtlp + (size_t)DM*DM);
    wtrans_kernel<<<wg, wb>>>(Wv, Wthp + (size_t)2*DM*DM, Wtlp + (size_t)2*DM*DM);
    wtrans_kernel<<<wg, wb>>>(Wo, Wthp + (size_t)3*DM*DM, Wtlp + (size_t)3*DM*DM);

    dim3 mmg(DM/128, MROWS/128);
    mm_kernel<<<mmg, 256, MM_SMEM>>>(Ahp, Alp, Wthp,                   Wtlp,                   nullptr, Qhp, Qlp, DM, 1);
    mm_kernel<<<mmg, 256, MM_SMEM>>>(Ahp, Alp, Wthp + (size_t)DM*DM,   Wtlp + (size_t)DM*DM,   nullptr, Khp, Klp, DM, 1);
    mm_kernel<<<mmg, 256, MM_SMEM>>>(Ahp, Alp, Wthp + (size_t)2*DM*DM, Wtlp + (size_t)2*DM*DM, nullptr, Vthp, Vtlp, DM, 2);

    dim3 fg(SS/128, NH, BB);
    flash_kernel<<<fg, 256, F_SMEM>>>(mask);

    mm_kernel<<<mmg, 256, MM_SMEM>>>(Chp, Clp, Wthp + (size_t)3*DM*DM, Wtlp + (size_t)3*DM*DM, out, nullptr, nullptr, DM, 0);
}